// round 10
// baseline (speedup 1.0000x reference)
#include <cuda_runtime.h>
#include <cuda.h>
#include <cuda_bf16.h>
#include <cstdint>

// LIF activation, forward:
//   decay[c] = 1 - w_leak[c]
//   gate  = (Vm < 1)  (strict)
//   Vm    = relu(x + decay*Vm*gate)
//   spike = (Vm > 1) ? 1 : 0  (strict)
// B=128, T=1000, C=512.
// R10: R7 pipeline (best so far) at finer CTA granularity: 128 channels/CTA,
// 128 threads, 512 CTAs -> 4 CTAs/SM (50KB smem each). Co-resident CTAs cover
// each other's barrier bubbles; smaller barriers (4 warps); finer tail.

namespace {
constexpr int B = 128;
constexpr int T = 1000;
constexpr int C = 512;
constexpr int CH = 128;                            // channels per CTA
constexpr int CHUNK_T = 20;                        // timesteps per chunk
constexpr int NCHUNKS = T / CHUNK_T;               // 50
constexpr uint32_t CH_BYTES = CHUNK_T * CH * 4;    // 10240
constexpr int IN_STAGES  = 3;
constexpr int OUT_STAGES = 2;
constexpr int THREADS = CH;                        // 128, one per channel

constexpr uint32_t SMEM_IN   = 0;
constexpr uint32_t SMEM_OUT  = IN_STAGES * CH_BYTES;               // 30720
constexpr uint32_t SMEM_MBAR = SMEM_OUT + OUT_STAGES * CH_BYTES;   // 51200
constexpr uint32_t SMEM_TOTAL = SMEM_MBAR + IN_STAGES * 8 + 64;
}

__device__ __forceinline__ uint32_t smem_u32(const void* p) {
    uint32_t a;
    asm("{ .reg .u64 t; cvta.to.shared.u64 t, %1; cvt.u32.u64 %0, t; }" : "=r"(a) : "l"(p));
    return a;
}
__device__ __forceinline__ uint64_t make_evict_first_policy() {
    uint64_t pol;
    asm("createpolicy.fractional.L2::evict_first.b64 %0, 1.0;" : "=l"(pol));
    return pol;
}
__device__ __forceinline__ void mbar_init(uint32_t mbar, uint32_t cnt) {
    asm volatile("mbarrier.init.shared.b64 [%0], %1;" :: "r"(mbar), "r"(cnt) : "memory");
}
__device__ __forceinline__ void mbar_expect_tx(uint32_t mbar, uint32_t bytes) {
    asm volatile("mbarrier.arrive.expect_tx.shared.b64 _, [%0], %1;" :: "r"(mbar), "r"(bytes) : "memory");
}
__device__ __forceinline__ void mbar_wait(uint32_t mbar, uint32_t parity) {
    uint32_t done;
    asm volatile(
        "{\n\t.reg .pred p;\n\t"
        "mbarrier.try_wait.parity.acquire.cta.shared::cta.b64 p, [%1], %2;\n\t"
        "selp.b32 %0, 1, 0, p;\n\t}"
        : "=r"(done) : "r"(mbar), "r"(parity) : "memory");
    while (!done) {
        asm volatile(
            "{\n\t.reg .pred p;\n\t"
            "mbarrier.try_wait.parity.acquire.cta.shared::cta.b64 p, [%1], %2, 0x989680;\n\t"
            "selp.b32 %0, 1, 0, p;\n\t}"
            : "=r"(done) : "r"(mbar), "r"(parity) : "memory");
    }
}
__device__ __forceinline__ void tma_load2d(uint32_t smem_dst, const CUtensorMap* map,
                                           int cx, int cy, uint32_t mbar, uint64_t pol) {
    asm volatile(
        "cp.async.bulk.tensor.2d.shared::cta.global.tile.mbarrier::complete_tx::bytes"
        ".L2::cache_hint [%0], [%1, {%2, %3}], [%4], %5;"
        :: "r"(smem_dst), "l"(map), "r"(cx), "r"(cy), "r"(mbar), "l"(pol) : "memory");
}
__device__ __forceinline__ void tma_store2d(const CUtensorMap* map, int cx, int cy,
                                            uint32_t smem_src, uint64_t pol) {
    asm volatile(
        "cp.async.bulk.tensor.2d.global.shared::cta.tile.bulk_group"
        ".L2::cache_hint [%0, {%1, %2}], [%3], %4;"
        :: "l"(map), "r"(cx), "r"(cy), "r"(smem_src), "l"(pol) : "memory");
}

__global__ void __launch_bounds__(THREADS, 4)
lif_kernel(const __grid_constant__ CUtensorMap in_map,
           const __grid_constant__ CUtensorMap out_map,
           const float* __restrict__ wl)
{
    extern __shared__ __align__(1024) char smem[];
    const uint32_t sbase = smem_u32(smem);
    const int tid = threadIdx.x;
    const int b   = blockIdx.x >> 2;
    const int c0  = (blockIdx.x & 3) << 7;     // 0,128,256,384
    const int c   = tid;

    const float d = 1.0f - wl[c0 + c];
    float v = 0.0f;

    const int ybase = b * T;                   // row in the [B*T, C] view
    const uint64_t pol = make_evict_first_policy();

    if (tid == 0) {
        #pragma unroll
        for (int s = 0; s < IN_STAGES; s++)
            mbar_init(sbase + SMEM_MBAR + s * 8, 1);
    }
    __syncthreads();

    // Prologue: fill the IN ring (chunks 0..2)
    if (tid == 0) {
        #pragma unroll
        for (int s = 0; s < IN_STAGES; s++) {
            const uint32_t mbar = sbase + SMEM_MBAR + s * 8;
            mbar_expect_tx(mbar, CH_BYTES);
            tma_load2d(sbase + SMEM_IN + s * CH_BYTES, &in_map,
                       c0, ybase + s * CHUNK_T, mbar, pol);
        }
    }

    int s = 0, parity = 0;
    for (int i = 0; i < NCHUNKS; i++) {
        const int o = i & (OUT_STAGES - 1);
        const uint32_t mbar = sbase + SMEM_MBAR + s * 8;

        // 1) Wait for input chunk i, pull it into registers.
        mbar_wait(mbar, (uint32_t)parity);

        const float* sin = (const float*)(smem + SMEM_IN + s * CH_BYTES);
        float xv[CHUNK_T];
        #pragma unroll
        for (int u = 0; u < CHUNK_T; u++)
            xv[u] = sin[u * CH + c];

        // 2) One sync covers: (a) every thread consumed smem-in stage s,
        //    (b) tid0's drain of the out-buffer we're about to overwrite.
        if (tid == 0)
            asm volatile("cp.async.bulk.wait_group.read 1;" ::: "memory");
        __syncthreads();

        // 3) Refill the consumed in-stage immediately (TMA loads during compute).
        if (tid == 0) {
            const int nxt = i + IN_STAGES;
            if (nxt < NCHUNKS) {
                mbar_expect_tx(mbar, CH_BYTES);
                tma_load2d(sbase + SMEM_IN + s * CH_BYTES, &in_map,
                           c0, ybase + nxt * CHUNK_T, mbar, pol);
            }
        }

        // 4) Serial recurrence, spikes into the out smem buffer.
        float* sout = (float*)(smem + SMEM_OUT + o * CH_BYTES);
        #pragma unroll
        for (int u = 0; u < CHUNK_T; u++) {
            v = fmaxf(0.0f, xv[u] + (v < 1.0f ? d * v : 0.0f));
            sout[u * CH + c] = (v > 1.0f) ? 1.0f : 0.0f;
        }

        __syncthreads();   // all spikes for chunk i in smem

        // 5) Bulk-store the chunk.
        if (tid == 0) {
            asm volatile("fence.proxy.async.shared::cta;" ::: "memory");
            tma_store2d(&out_map, c0, ybase + i * CHUNK_T,
                        sbase + SMEM_OUT + o * CH_BYTES, pol);
            asm volatile("cp.async.bulk.commit_group;" ::: "memory");
        }

        if (++s == IN_STAGES) { s = 0; parity ^= 1; }
    }

    if (tid == 0)
        asm volatile("cp.async.bulk.wait_group 0;" ::: "memory");
}

// ---------------- host ----------------

typedef CUresult (*PFN_encodeTiled)(
    CUtensorMap*, CUtensorMapDataType, cuuint32_t, void*,
    const cuuint64_t*, const cuuint64_t*, const cuuint32_t*, const cuuint32_t*,
    CUtensorMapInterleave, CUtensorMapSwizzle, CUtensorMapL2promotion,
    CUtensorMapFloatOOBfill);

static void make_map(PFN_encodeTiled enc, CUtensorMap* m, void* base) {
    cuuint64_t dims[2]    = {(cuuint64_t)C, (cuuint64_t)B * (cuuint64_t)T};
    cuuint64_t strides[1] = {(cuuint64_t)C * 4};
    cuuint32_t box[2]     = {(cuuint32_t)CH, (cuuint32_t)CHUNK_T};
    cuuint32_t estr[2]    = {1, 1};
    enc(m, CU_TENSOR_MAP_DATA_TYPE_FLOAT32, 2, base, dims, strides, box, estr,
        CU_TENSOR_MAP_INTERLEAVE_NONE, CU_TENSOR_MAP_SWIZZLE_NONE,
        CU_TENSOR_MAP_L2_PROMOTION_L2_256B, CU_TENSOR_MAP_FLOAT_OOB_FILL_NONE);
}

extern "C" void kernel_launch(void* const* d_in, const int* in_sizes, int n_in,
                              void* d_out, int out_size)
{
    void* x   = (void*)d_in[0];                 // x [B,T,C] f32
    const float* wl = (const float*)d_in[1];    // w_leak [C]

    PFN_encodeTiled enc = nullptr;
    {
        void* p = nullptr;
        cudaDriverEntryPointQueryResult qr;
        cudaGetDriverEntryPointByVersion("cuTensorMapEncodeTiled", &p, 12000,
                                         cudaEnableDefault, &qr);
        enc = (PFN_encodeTiled)p;
    }

    CUtensorMap in_map, out_map;
    make_map(enc, &in_map, x);
    make_map(enc, &out_map, d_out);

    cudaFuncSetAttribute(lif_kernel, cudaFuncAttributeMaxDynamicSharedMemorySize,
                         (int)SMEM_TOTAL);
    lif_kernel<<<B * 4, THREADS, SMEM_TOTAL>>>(in_map, out_map, wl);
}

// round 11
// speedup vs baseline: 1.0161x; 1.0161x over previous
#include <cuda_runtime.h>
#include <cuda_bf16.h>
#include <cstdint>

// LIF activation, forward:
//   decay[c] = 1 - w_leak[c]
//   gate  = (Vm < 1)  (strict)
//   Vm    = relu(x + decay*Vm*gate)
//   spike = (Vm > 1) ? 1 : 0  (strict)
// B=128, T=1000, C=512.
// R11: best-of-both. R4's fully-contiguous 1D bulk path (grid=128, 512 thr,
// full 2KB rows, 40KB contiguous chunks -> longest DRAM burst runs) with
// R7's tight loop (CHUNK_T=20, IN 3 + OUT 2 ring, drain folded into one
// sync, refill issued before compute). 50 chunks. No tensor maps needed.

namespace {
constexpr int B = 128;
constexpr int T = 1000;
constexpr int C = 512;
constexpr int CHUNK_T = 20;                        // timesteps per chunk
constexpr int NCHUNKS = T / CHUNK_T;               // 50
constexpr uint32_t CH_BYTES = CHUNK_T * C * 4;     // 40960
constexpr int IN_STAGES  = 3;
constexpr int OUT_STAGES = 2;
constexpr int THREADS = C;                         // 512, one per channel

constexpr uint32_t SMEM_IN   = 0;
constexpr uint32_t SMEM_OUT  = IN_STAGES * CH_BYTES;               // 122880
constexpr uint32_t SMEM_MBAR = SMEM_OUT + OUT_STAGES * CH_BYTES;   // 204800
constexpr uint32_t SMEM_TOTAL = SMEM_MBAR + IN_STAGES * 8 + 64;    // ~205KB
}

__device__ __forceinline__ uint32_t smem_u32(const void* p) {
    uint32_t a;
    asm("{ .reg .u64 t; cvta.to.shared.u64 t, %1; cvt.u32.u64 %0, t; }" : "=r"(a) : "l"(p));
    return a;
}
__device__ __forceinline__ void mbar_init(uint32_t mbar, uint32_t cnt) {
    asm volatile("mbarrier.init.shared.b64 [%0], %1;" :: "r"(mbar), "r"(cnt) : "memory");
}
__device__ __forceinline__ void mbar_expect_tx(uint32_t mbar, uint32_t bytes) {
    asm volatile("mbarrier.arrive.expect_tx.shared.b64 _, [%0], %1;" :: "r"(mbar), "r"(bytes) : "memory");
}
__device__ __forceinline__ void mbar_wait(uint32_t mbar, uint32_t parity) {
    uint32_t done;
    asm volatile(
        "{\n\t.reg .pred p;\n\t"
        "mbarrier.try_wait.parity.acquire.cta.shared::cta.b64 p, [%1], %2;\n\t"
        "selp.b32 %0, 1, 0, p;\n\t}"
        : "=r"(done) : "r"(mbar), "r"(parity) : "memory");
    while (!done) {
        asm volatile(
            "{\n\t.reg .pred p;\n\t"
            "mbarrier.try_wait.parity.acquire.cta.shared::cta.b64 p, [%1], %2, 0x989680;\n\t"
            "selp.b32 %0, 1, 0, p;\n\t}"
            : "=r"(done) : "r"(mbar), "r"(parity) : "memory");
    }
}
__device__ __forceinline__ void bulk_load(uint32_t smem_dst, const void* gmem_src,
                                          uint32_t bytes, uint32_t mbar) {
    asm volatile(
        "cp.async.bulk.shared::cta.global.mbarrier::complete_tx::bytes [%0], [%1], %2, [%3];"
        :: "r"(smem_dst), "l"(gmem_src), "r"(bytes), "r"(mbar) : "memory");
}
__device__ __forceinline__ void bulk_store(void* gmem_dst, uint32_t smem_src, uint32_t bytes) {
    asm volatile(
        "cp.async.bulk.global.shared::cta.bulk_group [%0], [%1], %2;"
        :: "l"(gmem_dst), "r"(smem_src), "r"(bytes) : "memory");
}

__global__ void __launch_bounds__(THREADS, 1)
lif_kernel(const float* __restrict__ x,
           const float* __restrict__ wl,
           float* __restrict__ out)
{
    extern __shared__ __align__(1024) char smem[];
    const uint32_t sbase = smem_u32(smem);
    const int tid = threadIdx.x;
    const int b   = blockIdx.x;
    const int c   = tid;                       // one thread per channel

    const float d = 1.0f - wl[c];
    float v = 0.0f;

    const float* __restrict__ xslab = x   + (size_t)b * T * C;   // 2MB contiguous
    float*       __restrict__ oslab = out + (size_t)b * T * C;

    if (tid == 0) {
        #pragma unroll
        for (int s = 0; s < IN_STAGES; s++)
            mbar_init(sbase + SMEM_MBAR + s * 8, 1);
    }
    __syncthreads();

    // Prologue: fill the IN ring (chunks 0..2) — 120KB of contiguous reads in flight.
    if (tid == 0) {
        #pragma unroll
        for (int s = 0; s < IN_STAGES; s++) {
            const uint32_t mbar = sbase + SMEM_MBAR + s * 8;
            mbar_expect_tx(mbar, CH_BYTES);
            bulk_load(sbase + SMEM_IN + s * CH_BYTES,
                      xslab + (size_t)s * CHUNK_T * C, CH_BYTES, mbar);
        }
    }

    int s = 0, parity = 0;
    for (int i = 0; i < NCHUNKS; i++) {
        const int o = i & (OUT_STAGES - 1);
        const uint32_t mbar = sbase + SMEM_MBAR + s * 8;

        // 1) Wait for input chunk i, pull this thread's column to registers.
        mbar_wait(mbar, (uint32_t)parity);

        const float* sin = (const float*)(smem + SMEM_IN + s * CH_BYTES);
        float xv[CHUNK_T];
        #pragma unroll
        for (int u = 0; u < CHUNK_T; u++)
            xv[u] = sin[u * C + c];

        // 2) One sync covers: (a) all threads consumed smem-in stage s,
        //    (b) tid0's drain of the out-buffer we're about to overwrite.
        if (tid == 0)
            asm volatile("cp.async.bulk.wait_group.read 1;" ::: "memory");
        __syncthreads();

        // 3) Refill the consumed in-stage immediately (loads run during compute).
        if (tid == 0) {
            const int nxt = i + IN_STAGES;
            if (nxt < NCHUNKS) {
                mbar_expect_tx(mbar, CH_BYTES);
                bulk_load(sbase + SMEM_IN + s * CH_BYTES,
                          xslab + (size_t)nxt * CHUNK_T * C, CH_BYTES, mbar);
            }
        }

        // 4) Serial recurrence, spikes into the out smem buffer.
        float* sout = (float*)(smem + SMEM_OUT + o * CH_BYTES);
        #pragma unroll
        for (int u = 0; u < CHUNK_T; u++) {
            v = fmaxf(0.0f, xv[u] + (v < 1.0f ? d * v : 0.0f));
            sout[u * C + c] = (v > 1.0f) ? 1.0f : 0.0f;
        }

        __syncthreads();   // all spikes for chunk i in smem

        // 5) Bulk-store the chunk: one 40KB fully-contiguous write burst.
        if (tid == 0) {
            asm volatile("fence.proxy.async.shared::cta;" ::: "memory");
            bulk_store(oslab + (size_t)i * CHUNK_T * C,
                       sbase + SMEM_OUT + o * CH_BYTES, CH_BYTES);
            asm volatile("cp.async.bulk.commit_group;" ::: "memory");
        }

        if (++s == IN_STAGES) { s = 0; parity ^= 1; }
    }

    if (tid == 0)
        asm volatile("cp.async.bulk.wait_group 0;" ::: "memory");
}

extern "C" void kernel_launch(void* const* d_in, const int* in_sizes, int n_in,
                              void* d_out, int out_size)
{
    const float* x  = (const float*)d_in[0];   // x [B,T,C]
    const float* wl = (const float*)d_in[1];   // w_leak [C]
    float* out      = (float*)d_out;

    cudaFuncSetAttribute(lif_kernel, cudaFuncAttributeMaxDynamicSharedMemorySize,
                         (int)SMEM_TOTAL);
    lif_kernel<<<B, THREADS, SMEM_TOTAL>>>(x, wl, out);
}